// round 4
// baseline (speedup 1.0000x reference)
#include <cuda_runtime.h>
#include <math.h>
#include <stdint.h>

#define N_NODES 100000
#define E_EDGES 1600000
#define K_IN    192
#define F_LAT   64
#define F_OUT   128
#define NB_SCAN ((N_NODES + 1023) / 1024)   // 98

typedef unsigned long long ull;

// ---------------------------------------------------------------------------
// Scratch (device globals)
// ---------------------------------------------------------------------------
__device__ float4 g_feat4[N_NODES * (F_OUT / 4)];   // feat [N,128]
__device__ float  g_el[N_NODES];
__device__ float  g_er[N_NODES];
__device__ int    g_cnt[N_NODES];                   // in-degree
__device__ int    g_start[N_NODES];                 // CSR offsets
__device__ int    g_cursor[N_NODES];                // scatter cursors
__device__ int    g_bsum[NB_SCAN];
__device__ int    g_boff[NB_SCAN];
__device__ int2   g_pairS[E_EDGES];                 // dst-sorted (src, float-bits(ee))

// ---------------------------------------------------------------------------
// Packed f32x2 helpers (Blackwell 2x fp32 path; ptxas never auto-emits this)
// ---------------------------------------------------------------------------
__device__ __forceinline__ ull pack2(float a, float b) {
    ull r; asm("mov.b64 %0, {%1, %2};" : "=l"(r) : "f"(a), "f"(b)); return r;
}
__device__ __forceinline__ void fma2(ull& d, ull a, ull b) {
    asm("fma.rn.f32x2 %0, %1, %2, %0;" : "+l"(d) : "l"(a), "l"(b));
}
__device__ __forceinline__ void unpack2(float& lo, float& hi, ull v) {
    asm("mov.b64 {%0, %1}, %2;" : "=f"(lo), "=f"(hi) : "l"(v));
}

// ---------------------------------------------------------------------------
// Fused node kernel: x = relu(embed@W1+b); feat = x@W2; el/er dots.
// 64-node tile, 256 threads, 4x4 microtile done as 4x(2x f32x2).
// Also zeroes the in-degree histogram (64 entries per block).
// ---------------------------------------------------------------------------
__global__ void __launch_bounds__(256) node_kernel(const float* __restrict__ embed,
                                                   const float* __restrict__ Wl,
                                                   const float* __restrict__ bl,
                                                   const float* __restrict__ Wg,
                                                   const float* __restrict__ attn_l,
                                                   const float* __restrict__ attn_r) {
    __shared__ float sA[64][68];
    __shared__ float sW[64][64];
    __shared__ float sEl[64];
    __shared__ float sEr[64];

    int t = threadIdx.x;
    int base = blockIdx.x * 64;
    int tm = t >> 4;
    int tn = t & 15;

    if (t < 64) {
        sEl[t] = 0.f; sEr[t] = 0.f;
        int node = base + t;
        if (node < N_NODES) g_cnt[node] = 0;      // fold zero_cnt in here
    }

    ull acc[4][2];   // 4 rows x 4 cols as 2 packed pairs
#pragma unroll
    for (int r = 0; r < 4; r++) { acc[r][0] = 0ull; acc[r][1] = 0ull; }

    // ---- phase A: x = relu(embed @ W_lin + b) ----
    for (int kc = 0; kc < 3; kc++) {
#pragma unroll
        for (int l = 0; l < 4; l++) {
            int idx = l * 256 + t;
            int r = idx >> 4;
            int c = (idx & 15) * 4;
            int node = base + r;
            float4 v = make_float4(0.f, 0.f, 0.f, 0.f);
            if (node < N_NODES)
                v = *reinterpret_cast<const float4*>(&embed[(size_t)node * K_IN + kc * 64 + c]);
            *reinterpret_cast<float4*>(&sA[r][c]) = v;
            float4 w = *reinterpret_cast<const float4*>(&Wl[(size_t)kc * 4096 + idx * 4]);
            *reinterpret_cast<float4*>(&sW[0][0] + idx * 4) = w;
        }
        __syncthreads();

#pragma unroll 16
        for (int k = 0; k < 64; k++) {
            ull pa0 = pack2(sA[tm * 4 + 0][k], sA[tm * 4 + 0][k]);
            ull pa1 = pack2(sA[tm * 4 + 1][k], sA[tm * 4 + 1][k]);
            ull pa2 = pack2(sA[tm * 4 + 2][k], sA[tm * 4 + 2][k]);
            ull pa3 = pack2(sA[tm * 4 + 3][k], sA[tm * 4 + 3][k]);
            ulonglong2 bb = *reinterpret_cast<const ulonglong2*>(&sW[k][tn * 4]);
            fma2(acc[0][0], pa0, bb.x); fma2(acc[0][1], pa0, bb.y);
            fma2(acc[1][0], pa1, bb.x); fma2(acc[1][1], pa1, bb.y);
            fma2(acc[2][0], pa2, bb.x); fma2(acc[2][1], pa2, bb.y);
            fma2(acc[3][0], pa3, bb.x); fma2(acc[3][1], pa3, bb.y);
        }
        __syncthreads();
    }

    {
        float4 bias = *reinterpret_cast<const float4*>(&bl[tn * 4]);
#pragma unroll
        for (int r = 0; r < 4; r++) {
            float c0, c1, c2, c3;
            unpack2(c0, c1, acc[r][0]);
            unpack2(c2, c3, acc[r][1]);
            sA[tm * 4 + r][tn * 4 + 0] = fmaxf(c0 + bias.x, 0.f);
            sA[tm * 4 + r][tn * 4 + 1] = fmaxf(c1 + bias.y, 0.f);
            sA[tm * 4 + r][tn * 4 + 2] = fmaxf(c2 + bias.z, 0.f);
            sA[tm * 4 + r][tn * 4 + 3] = fmaxf(c3 + bias.w, 0.f);
        }
    }
    __syncthreads();

    // ---- phase B: feat = x @ W_gat (two 64-wide halves), el/er dots ----
    for (int nh = 0; nh < 2; nh++) {
#pragma unroll
        for (int l = 0; l < 4; l++) {
            int idx = l * 256 + t;
            int r = idx >> 4;
            int c = (idx & 15) * 4;
            float4 w = *reinterpret_cast<const float4*>(&Wg[(size_t)r * F_OUT + nh * 64 + c]);
            *reinterpret_cast<float4*>(&sW[0][0] + r * 64 + c) = w;
        }
        __syncthreads();

#pragma unroll
        for (int r = 0; r < 4; r++) { acc[r][0] = 0ull; acc[r][1] = 0ull; }

#pragma unroll 16
        for (int k = 0; k < 64; k++) {
            ull pa0 = pack2(sA[tm * 4 + 0][k], sA[tm * 4 + 0][k]);
            ull pa1 = pack2(sA[tm * 4 + 1][k], sA[tm * 4 + 1][k]);
            ull pa2 = pack2(sA[tm * 4 + 2][k], sA[tm * 4 + 2][k]);
            ull pa3 = pack2(sA[tm * 4 + 3][k], sA[tm * 4 + 3][k]);
            ulonglong2 bb = *reinterpret_cast<const ulonglong2*>(&sW[k][tn * 4]);
            fma2(acc[0][0], pa0, bb.x); fma2(acc[0][1], pa0, bb.y);
            fma2(acc[1][0], pa1, bb.x); fma2(acc[1][1], pa1, bb.y);
            fma2(acc[2][0], pa2, bb.x); fma2(acc[2][1], pa2, bb.y);
            fma2(acc[3][0], pa3, bb.x); fma2(acc[3][1], pa3, bb.y);
        }

        float4 al = *reinterpret_cast<const float4*>(&attn_l[nh * 64 + tn * 4]);
        float4 ar = *reinterpret_cast<const float4*>(&attn_r[nh * 64 + tn * 4]);
#pragma unroll
        for (int r = 0; r < 4; r++) {
            int node = base + tm * 4 + r;
            if (node < N_NODES) {
                float4 o;
                unpack2(o.x, o.y, acc[r][0]);
                unpack2(o.z, o.w, acc[r][1]);
                g_feat4[(size_t)node * (F_OUT / 4) + (nh * 16 + tn)] = o;
                float pl = o.x * al.x + o.y * al.y + o.z * al.z + o.w * al.w;
                float pr = o.x * ar.x + o.y * ar.y + o.z * ar.z + o.w * ar.w;
                atomicAdd(&sEl[tm * 4 + r], pl);
                atomicAdd(&sEr[tm * 4 + r], pr);
            }
        }
        __syncthreads();
    }

    if (t < 64) {
        int node = base + t;
        if (node < N_NODES) {
            g_el[node] = sEl[t];
            g_er[node] = sEr[t];
        }
    }
}

// ---------------------------------------------------------------------------
// CSR build step 1: in-degree histogram of dst
// ---------------------------------------------------------------------------
__global__ void __launch_bounds__(256) hist_kernel(const int* __restrict__ dst,
                                                   int num_edges) {
    int i = blockIdx.x * 256 + threadIdx.x;
    int stride = gridDim.x * 256;
    for (int e = i; e < num_edges; e += stride)
        atomicAdd(&g_cnt[dst[e]], 1);
}

// ---------------------------------------------------------------------------
// CSR build step 2: exclusive scan
// ---------------------------------------------------------------------------
__global__ void __launch_bounds__(1024) scan_blocks() {
    __shared__ int sw[32];
    int tid = threadIdx.x;
    int lane = tid & 31;
    int wid = tid >> 5;
    int i = blockIdx.x * 1024 + tid;
    int v = (i < N_NODES) ? g_cnt[i] : 0;

    int x = v;
#pragma unroll
    for (int d = 1; d < 32; d <<= 1) {
        int y = __shfl_up_sync(0xffffffffu, x, d);
        if (lane >= d) x += y;
    }
    if (lane == 31) sw[wid] = x;
    __syncthreads();
    if (wid == 0) {
        int s = sw[lane];
#pragma unroll
        for (int d = 1; d < 32; d <<= 1) {
            int y = __shfl_up_sync(0xffffffffu, s, d);
            if (lane >= d) s += y;
        }
        sw[lane] = s;
    }
    __syncthreads();
    int incl = x + (wid > 0 ? sw[wid - 1] : 0);
    if (i < N_NODES) g_start[i] = incl - v;
    if (tid == 1023) g_bsum[blockIdx.x] = incl;
}

__global__ void scan_tops() {
    if (threadIdx.x == 0 && blockIdx.x == 0) {
        int run = 0;
        for (int b = 0; b < NB_SCAN; b++) {
            g_boff[b] = run;
            run += g_bsum[b];
        }
    }
}

__global__ void __launch_bounds__(256) scan_apply() {
    int i = blockIdx.x * 256 + threadIdx.x;
    if (i < N_NODES) {
        int s = g_start[i] + g_boff[i >> 10];
        g_start[i] = s;
        g_cursor[i] = s;
    }
}

// ---------------------------------------------------------------------------
// CSR build step 3: compute ee per edge, scatter (src, ee) into dst order
// ---------------------------------------------------------------------------
__global__ void __launch_bounds__(256) scatter_kernel(const int* __restrict__ src,
                                                      const int* __restrict__ dst,
                                                      int num_edges) {
    int i = blockIdx.x * 256 + threadIdx.x;
    int stride = gridDim.x * 256;
    for (int e = i; e < num_edges; e += stride) {
        int s = src[e];
        int d = dst[e];
        float logit = g_el[s] + g_er[d];
        logit = (logit > 0.f) ? logit : 0.2f * logit;
        float ee = __expf(logit);
        int pos = atomicAdd(&g_cursor[d], 1);
        g_pairS[pos] = make_int2(s, __float_as_int(ee));
    }
}

// ---------------------------------------------------------------------------
// Aggregation: one warp per dst node; gather + normalize + bias + tanh,
// write final output directly. Lane l owns float4 columns [4l, 4l+4).
// ---------------------------------------------------------------------------
__global__ void __launch_bounds__(256) agg_kernel(const float* __restrict__ b_gat,
                                                  float* __restrict__ out) {
    int warp = (blockIdx.x * 256 + threadIdx.x) >> 5;
    int lane = threadIdx.x & 31;
    if (warp >= N_NODES) return;

    int beg = g_start[warp];
    int deg = g_cnt[warp];
    int end = beg + deg;

    float4 acc = make_float4(0.f, 0.f, 0.f, 0.f);
    float dsum = 0.f;

    int j = beg;
    for (; j + 4 <= end; j += 4) {
        int2 p0 = g_pairS[j + 0];
        int2 p1 = g_pairS[j + 1];
        int2 p2 = g_pairS[j + 2];
        int2 p3 = g_pairS[j + 3];
        float e0 = __int_as_float(p0.y), e1 = __int_as_float(p1.y);
        float e2 = __int_as_float(p2.y), e3 = __int_as_float(p3.y);
        float4 f0 = g_feat4[(size_t)p0.x * 32 + lane];
        float4 f1 = g_feat4[(size_t)p1.x * 32 + lane];
        float4 f2 = g_feat4[(size_t)p2.x * 32 + lane];
        float4 f3 = g_feat4[(size_t)p3.x * 32 + lane];
        acc.x += e0 * f0.x + e1 * f1.x + e2 * f2.x + e3 * f3.x;
        acc.y += e0 * f0.y + e1 * f1.y + e2 * f2.y + e3 * f3.y;
        acc.z += e0 * f0.z + e1 * f1.z + e2 * f2.z + e3 * f3.z;
        acc.w += e0 * f0.w + e1 * f1.w + e2 * f2.w + e3 * f3.w;
        dsum += (e0 + e1) + (e2 + e3);
    }
    for (; j < end; j++) {
        int2 p = g_pairS[j];
        float ee = __int_as_float(p.y);
        float4 f = g_feat4[(size_t)p.x * 32 + lane];
        acc.x += ee * f.x; acc.y += ee * f.y; acc.z += ee * f.z; acc.w += ee * f.w;
        dsum += ee;
    }

    float inv = (dsum > 0.f) ? (1.0f / dsum) : 0.f;
    float4 bg = *reinterpret_cast<const float4*>(&b_gat[lane * 4]);
    float4 y = make_float4(acc.x * inv + bg.x, acc.y * inv + bg.y,
                           acc.z * inv + bg.z, acc.w * inv + bg.w);

    if (lane < 16) {
        *reinterpret_cast<float4*>(&out[(size_t)warp * 64 + lane * 4]) = y;
    } else {
        float4 z = make_float4(tanhf(y.x), tanhf(y.y), tanhf(y.z), tanhf(y.w));
        *reinterpret_cast<float4*>(&out[(size_t)N_NODES * 64 + (size_t)warp * 64 + (lane - 16) * 4]) = z;
    }
}

// ---------------------------------------------------------------------------
// Launch
// ---------------------------------------------------------------------------
extern "C" void kernel_launch(void* const* d_in, const int* in_sizes, int n_in,
                              void* d_out, int out_size) {
    const float* embed  = (const float*)d_in[0];
    const int*   src    = (const int*)d_in[1];
    const int*   dst    = (const int*)d_in[2];
    const float* W_lin  = (const float*)d_in[3];
    const float* b_lin  = (const float*)d_in[4];
    const float* W_gat  = (const float*)d_in[5];
    const float* attn_l = (const float*)d_in[6];
    const float* attn_r = (const float*)d_in[7];
    const float* b_gat  = (const float*)d_in[8];
    float* out = (float*)d_out;

    int num_edges = in_sizes[1];   // E

    node_kernel<<<(N_NODES + 63) / 64, 256>>>(embed, W_lin, b_lin, W_gat, attn_l, attn_r);
    hist_kernel<<<1184, 256>>>(dst, num_edges);
    scan_blocks<<<NB_SCAN, 1024>>>();
    scan_tops<<<1, 32>>>();
    scan_apply<<<(N_NODES + 255) / 256, 256>>>();
    scatter_kernel<<<1184, 256>>>(src, dst, num_edges);
    agg_kernel<<<(N_NODES * 32 + 255) / 256, 256>>>(b_gat, out);
}